// round 16
// baseline (speedup 1.0000x reference)
#include <cuda_runtime.h>

#define B_ 4096
#define N_ 64
#define H_ 256
#define TB3 16

#define NB_GEMM 640   // 64 b-tiles x 5 m-tiles x 2 K-splits (64x64, K=128 each)
#define NB_UV   2048
#define NB_K3   1024

typedef unsigned long long u64;

// Scratch (allocation-free rule: __device__ globals)
__device__ float g_UV[N_ * H_];      //  64 KiB
__device__ float g_sW0[B_ * H_];     //   4 MiB (K half 0)
__device__ float g_sW1[B_ * H_];     //   4 MiB (K half 1)
__device__ float g_gl0[B_ * N_];     //   1 MiB (gate logits half 0)
__device__ float g_gl1[B_ * N_];     //   1 MiB (gate logits half 1)
__device__ int g_flag_w[64];         // per 64-b tile: 10 producer blocks each
__device__ int g_flag_uv[4];         // per 16-n tile: 512 producer blocks each

// ---------- packed fp32x2 helpers (sm_103a FFMA2) ----------
__device__ __forceinline__ u64 pack2(float x, float y) {
    u64 r; asm("mov.b64 %0, {%1, %2};" : "=l"(r) : "f"(x), "f"(y)); return r;
}
__device__ __forceinline__ u64 fma2(u64 a, u64 b, u64 c) {
    u64 d; asm("fma.rn.f32x2 %0, %1, %2, %3;" : "=l"(d) : "l"(a), "l"(b), "l"(c)); return d;
}
__device__ __forceinline__ float2 unpack2(u64 v) {
    float2 r; asm("mov.b64 {%0, %1}, %2;" : "=f"(r.x), "=f"(r.y) : "l"(v)); return r;
}

__global__ void k_reset() {
    const int t = threadIdx.x;
    if (t < 64) g_flag_w[t] = 0;
    else if (t < 68) g_flag_uv[t - 64] = 0;
}

__device__ __forceinline__ void row_step(const float4 uv, const float4 hh,
                                         const float4 sw, const float g,
                                         const float a, float4& o, float& ss)
{
    float c, t;
    c = uv.x + sw.x; c = (c >= 0.f) ? c : a * c; t = fmaf(g, c, hh.x); o.x = t; ss = fmaf(t, t, ss);
    c = uv.y + sw.y; c = (c >= 0.f) ? c : a * c; t = fmaf(g, c, hh.y); o.y = t; ss = fmaf(t, t, ss);
    c = uv.z + sw.z; c = (c >= 0.f) ? c : a * c; t = fmaf(g, c, hh.z); o.z = t; ss = fmaf(t, t, ss);
    c = uv.w + sw.w; c = (c >= 0.f) ? c : a * c; t = fmaf(g, c, hh.w); o.w = t; ss = fmaf(t, t, ss);
}

// ---------------------------------------------------------------------------
// Mega kernel, one launch, three roles by blockIdx.x (producers first):
//  [0,640):      split-K GEMM: tile = blk>>1, ks = blk&1, K=128 per block
//                (4 chunks -> per-block critical path HALVED vs R15).
//                C_ks -> g_sW{ks} / g_gl{ks}; ++g_flag_w[b-tile] (to 10).
//  [640,2688):   UV (warp per element) -> g_UV; ++g_flag_uv[n/16] (to 512).
//  [2688,3712):  k3 (R2 body); volatile-load spin, staging sums the halves
//                and applies sigmoid to the summed gate logits.
// Deadlock-free: producers have lower blockIdx and never wait.
// ---------------------------------------------------------------------------
__global__ void __launch_bounds__(256) mega(
    const float* __restrict__ s, const float* __restrict__ W,
    const float* __restrict__ h, const float* __restrict__ w,
    const float* __restrict__ U, const float* __restrict__ V,
    const float* __restrict__ a_ptr, float* __restrict__ out)
{
    __shared__ union {
        struct { float sa[32][64]; float sb[32][64]; } g;      // 16 KiB
        struct { float4 sw[2][64]; float gt[2][16]; } c;       //  2.2 KiB
    } sm;

    const int tid = threadIdx.x;
    const int blk = blockIdx.x;

    if (blk < NB_GEMM) {
        // ================= split-K GEMM =================
        const int tile = blk >> 1;
        const int ks = blk & 1;
        const int kbase = ks * 128;
        const int mx = tile % 5;
        const int b0 = (tile / 5) * 64;
        const int m0 = mx * 64;
        const bool gate_tile = (mx == 4);
        float* __restrict__ outW = ks ? g_sW1 : g_sW0;
        float* __restrict__ outG = ks ? g_gl1 : g_gl0;

        const int row = tid & 63;
        const int kq = (tid >> 6) << 2;
        const int tx = tid & 15;
        const int ty = tid >> 4;
        const int rb = ty << 2;
        const int cm = tx << 2;

        u64 acc2[2][4] = {};

        float4 ra0, ra1, rb0, rb1;
        ra0 = *(const float4*)&s[(b0 + row) * H_ + kbase + kq];
        ra1 = *(const float4*)&s[(b0 + row) * H_ + kbase + 16 + kq];
        if (!gate_tile) {
            rb0 = *(const float4*)&W[(m0 + row) * H_ + kbase + kq];
            rb1 = *(const float4*)&W[(m0 + row) * H_ + kbase + 16 + kq];
        } else {
            float4 x0 = *(const float4*)&h[row * H_ + kbase + kq];
            float4 x1 = *(const float4*)&h[row * H_ + kbase + 16 + kq];
            float4 y0 = *(const float4*)&w[row * H_ + kbase + kq];
            float4 y1 = *(const float4*)&w[row * H_ + kbase + 16 + kq];
            rb0 = make_float4(x0.x + y0.x, x0.y + y0.y, x0.z + y0.z, x0.w + y0.w);
            rb1 = make_float4(x1.x + y1.x, x1.y + y1.y, x1.z + y1.z, x1.w + y1.w);
        }

        for (int kc = 0; kc < 128; kc += 32) {
            sm.g.sa[kq + 0][row] = ra0.x; sm.g.sa[kq + 1][row] = ra0.y;
            sm.g.sa[kq + 2][row] = ra0.z; sm.g.sa[kq + 3][row] = ra0.w;
            sm.g.sa[16 + kq + 0][row] = ra1.x; sm.g.sa[16 + kq + 1][row] = ra1.y;
            sm.g.sa[16 + kq + 2][row] = ra1.z; sm.g.sa[16 + kq + 3][row] = ra1.w;
            sm.g.sb[kq + 0][row] = rb0.x; sm.g.sb[kq + 1][row] = rb0.y;
            sm.g.sb[kq + 2][row] = rb0.z; sm.g.sb[kq + 3][row] = rb0.w;
            sm.g.sb[16 + kq + 0][row] = rb1.x; sm.g.sb[16 + kq + 1][row] = rb1.y;
            sm.g.sb[16 + kq + 2][row] = rb1.z; sm.g.sb[16 + kq + 3][row] = rb1.w;
            __syncthreads();

            if (kc + 32 < 128) {
                const int kn = kbase + kc + 32;
                ra0 = *(const float4*)&s[(b0 + row) * H_ + kn + kq];
                ra1 = *(const float4*)&s[(b0 + row) * H_ + kn + 16 + kq];
                if (!gate_tile) {
                    rb0 = *(const float4*)&W[(m0 + row) * H_ + kn + kq];
                    rb1 = *(const float4*)&W[(m0 + row) * H_ + kn + 16 + kq];
                } else {
                    float4 x0 = *(const float4*)&h[row * H_ + kn + kq];
                    float4 x1 = *(const float4*)&h[row * H_ + kn + 16 + kq];
                    float4 y0 = *(const float4*)&w[row * H_ + kn + kq];
                    float4 y1 = *(const float4*)&w[row * H_ + kn + 16 + kq];
                    rb0 = make_float4(x0.x + y0.x, x0.y + y0.y, x0.z + y0.z, x0.w + y0.w);
                    rb1 = make_float4(x1.x + y1.x, x1.y + y1.y, x1.z + y1.z, x1.w + y1.w);
                }
            }

#pragma unroll 8
            for (int k = 0; k < 32; ++k) {
                const ulonglong2 a2 = *(const ulonglong2*)&sm.g.sa[k][rb];
                const float4 bv = *(const float4*)&sm.g.sb[k][cm];
                u64 bx = pack2(bv.x, bv.x);
                u64 by = pack2(bv.y, bv.y);
                u64 bz = pack2(bv.z, bv.z);
                u64 bw = pack2(bv.w, bv.w);
                acc2[0][0] = fma2(a2.x, bx, acc2[0][0]);
                acc2[0][1] = fma2(a2.x, by, acc2[0][1]);
                acc2[0][2] = fma2(a2.x, bz, acc2[0][2]);
                acc2[0][3] = fma2(a2.x, bw, acc2[0][3]);
                acc2[1][0] = fma2(a2.y, bx, acc2[1][0]);
                acc2[1][1] = fma2(a2.y, by, acc2[1][1]);
                acc2[1][2] = fma2(a2.y, bz, acc2[1][2]);
                acc2[1][3] = fma2(a2.y, bw, acc2[1][3]);
            }
            __syncthreads();
        }

#pragma unroll
        for (int ib = 0; ib < 2; ++ib) {
            float2 c0 = unpack2(acc2[ib][0]);
            float2 c1 = unpack2(acc2[ib][1]);
            float2 c2 = unpack2(acc2[ib][2]);
            float2 c3 = unpack2(acc2[ib][3]);
            const int bA = b0 + rb + 2 * ib;
            if (!gate_tile) {
                *(float4*)&outW[bA * H_ + m0 + cm] = make_float4(c0.x, c1.x, c2.x, c3.x);
                *(float4*)&outW[(bA + 1) * H_ + m0 + cm] = make_float4(c0.y, c1.y, c2.y, c3.y);
            } else {
                *(float4*)&outG[bA * N_ + cm] = make_float4(c0.x, c1.x, c2.x, c3.x);
                *(float4*)&outG[(bA + 1) * N_ + cm] = make_float4(c0.y, c1.y, c2.y, c3.y);
            }
        }
        __threadfence();
        __syncthreads();
        if (tid == 0) atomicAdd(&g_flag_w[tile / 5], 1);

    } else if (blk < NB_GEMM + NB_UV) {
        // ================= UV =================
        const int id = blk - NB_GEMM;
        const int n = id >> 5;
        const int kg = id & 31;
        const int warp = tid >> 5;
        const int lane = tid & 31;
        const int k = kg * 8 + warp;
        const int off = lane * 8;

        const float4* u4 = (const float4*)(U + k * H_ + off);
        const float4* v4 = (const float4*)(V + k * H_ + off);
        const float4* h4 = (const float4*)(h + n * H_ + off);
        const float4* w4 = (const float4*)(w + n * H_ + off);
        float4 u0 = u4[0], u1 = u4[1];
        float4 v0 = v4[0], v1 = v4[1];
        float4 x0 = __ldg(h4), x1 = __ldg(h4 + 1);
        float4 y0 = __ldg(w4), y1 = __ldg(w4 + 1);

        float acc = 0.f;
        acc = fmaf(u0.x, x0.x, acc); acc = fmaf(u0.y, x0.y, acc);
        acc = fmaf(u0.z, x0.z, acc); acc = fmaf(u0.w, x0.w, acc);
        acc = fmaf(u1.x, x1.x, acc); acc = fmaf(u1.y, x1.y, acc);
        acc = fmaf(u1.z, x1.z, acc); acc = fmaf(u1.w, x1.w, acc);
        acc = fmaf(v0.x, y0.x, acc); acc = fmaf(v0.y, y0.y, acc);
        acc = fmaf(v0.z, y0.z, acc); acc = fmaf(v0.w, y0.w, acc);
        acc = fmaf(v1.x, y1.x, acc); acc = fmaf(v1.y, y1.y, acc);
        acc = fmaf(v1.w, y1.w, acc); acc = fmaf(v1.z, y1.z, acc);

#pragma unroll
        for (int o = 16; o > 0; o >>= 1)
            acc += __shfl_xor_sync(0xFFFFFFFFu, acc, o);
        if (lane == 0) g_UV[n * H_ + k] = acc;

        __threadfence();
        __syncthreads();
        if (tid == 0) atomicAdd(&g_flag_uv[n >> 4], 1);

    } else {
        // ================= k3 (consumer, R2 body + summed staging) =========
        const int id = blk - (NB_GEMM + NB_UV);
        const int n0 = (id & 3) * 16;
        const int b0 = (id >> 2) * TB3;
        const int bt = b0 >> 6;

        const int warp = tid >> 5;
        const int lane = tid & 31;
        const int nA = n0 + warp;
        const int nB = n0 + warp + 8;
        const int k0 = lane * 4;
        const int k1 = 128 + lane * 4;

        // Pure inputs: load before waiting (overlaps the spin).
        float4 hA0 = __ldg((const float4*)&h[nA * H_ + k0]);
        float4 hA1 = __ldg((const float4*)&h[nA * H_ + k1]);
        float4 hB0 = __ldg((const float4*)&h[nB * H_ + k0]);
        float4 hB1 = __ldg((const float4*)&h[nB * H_ + k1]);
        const float a = __ldg(a_ptr);

        // Volatile-load spin with backoff (no atomic storm).
        if (tid == 0) {
            while (((volatile int*)g_flag_w)[bt] < 10) __nanosleep(128);
            while (((volatile int*)g_flag_uv)[n0 >> 4] < 512) __nanosleep(128);
            __threadfence();
        }
        __syncthreads();

        float4 uvA0 = *(const float4*)&g_UV[nA * H_ + k0];
        float4 uvA1 = *(const float4*)&g_UV[nA * H_ + k1];
        float4 uvB0 = *(const float4*)&g_UV[nB * H_ + k0];
        float4 uvB1 = *(const float4*)&g_UV[nB * H_ + k1];

        if (tid < 64) {
            float4 p = __ldg((const float4*)&g_sW0[(size_t)b0 * H_] + tid);
            float4 q = __ldg((const float4*)&g_sW1[(size_t)b0 * H_] + tid);
            sm.c.sw[0][tid] = make_float4(p.x + q.x, p.y + q.y, p.z + q.z, p.w + q.w);
        } else if (tid < 80) {
            const int j = b0 * N_ + n0 + (tid - 64);
            sm.c.gt[0][tid - 64] = 1.0f / (1.0f + __expf(-(__ldg(&g_gl0[j]) + __ldg(&g_gl1[j]))));
        }
        __syncthreads();

        for (int i = 0; i < TB3; ++i) {
            const int buf = i & 1;
            if (i + 1 < TB3) {
                const int bn = b0 + i + 1;
                if (tid < 64) {
                    float4 p = __ldg((const float4*)&g_sW0[(size_t)bn * H_] + tid);
                    float4 q = __ldg((const float4*)&g_sW1[(size_t)bn * H_] + tid);
                    sm.c.sw[buf ^ 1][tid] = make_float4(p.x + q.x, p.y + q.y, p.z + q.z, p.w + q.w);
                } else if (tid < 80) {
                    const int j = bn * N_ + n0 + (tid - 64);
                    sm.c.gt[buf ^ 1][tid - 64] =
                        1.0f / (1.0f + __expf(-(__ldg(&g_gl0[j]) + __ldg(&g_gl1[j]))));
                }
            }

            const float4 s0 = sm.c.sw[buf][lane];
            const float4 s1 = sm.c.sw[buf][lane + 32];
            const float gA = sm.c.gt[buf][warp];
            const float gB = sm.c.gt[buf][warp + 8];

            float4 oA0, oA1, oB0, oB1;
            float ssA = 0.f, ssB = 0.f;
            row_step(uvA0, hA0, s0, gA, a, oA0, ssA);
            row_step(uvA1, hA1, s1, gA, a, oA1, ssA);
            row_step(uvB0, hB0, s0, gB, a, oB0, ssB);
            row_step(uvB1, hB1, s1, gB, a, oB1, ssB);

#pragma unroll
            for (int o = 16; o > 0; o >>= 1) {
                ssA += __shfl_xor_sync(0xFFFFFFFFu, ssA, o);
                ssB += __shfl_xor_sync(0xFFFFFFFFu, ssB, o);
            }
            const float iA = rsqrtf(ssA);
            const float iB = rsqrtf(ssB);

            const int b = b0 + i;
            float4* oA = (float4*)&out[((size_t)b * N_ + nA) * H_];
            float4* oB = (float4*)&out[((size_t)b * N_ + nB) * H_];
            oA[lane]      = make_float4(oA0.x * iA, oA0.y * iA, oA0.z * iA, oA0.w * iA);
            oA[32 + lane] = make_float4(oA1.x * iA, oA1.y * iA, oA1.z * iA, oA1.w * iA);
            oB[lane]      = make_float4(oB0.x * iB, oB0.y * iB, oB0.z * iB, oB0.w * iB);
            oB[32 + lane] = make_float4(oB1.x * iB, oB1.y * iB, oB1.z * iB, oB1.w * iB);

            __syncthreads();
        }
    }
}

// ---------------------------------------------------------------------------
extern "C" void kernel_launch(void* const* d_in, const int* in_sizes, int n_in,
                              void* d_out, int out_size)
{
    const float* s_t = (const float*)d_in[0];   // [B,H]
    const float* h   = (const float*)d_in[1];   // [1,N,H]
    const float* w   = (const float*)d_in[2];   // [1,N,H]
    const float* U   = (const float*)d_in[3];   // [H,H]
    const float* V   = (const float*)d_in[4];   // [H,H]
    const float* W   = (const float*)d_in[5];   // [H,H]
    const float* pa  = (const float*)d_in[6];   // [1]
    float* out = (float*)d_out;                 // [B,N,H]

    k_reset<<<1, 128>>>();
    mega<<<NB_GEMM + NB_UV + NB_K3, 256>>>(s_t, W, h, w, U, V, pa, out);
}

// round 17
// speedup vs baseline: 1.0618x; 1.0618x over previous
#include <cuda_runtime.h>

#define B_ 4096
#define N_ 64
#define H_ 256
#define TB3 16

#define NB_GEMM 640   // 64 b-tiles x 10 m-subtiles (64b x 32m, K=256)
#define NB_UV   2048
#define NB_K3   1024

typedef unsigned long long u64;

// Scratch (allocation-free rule: __device__ globals)
__device__ float g_UV[N_ * H_];     //  64 KiB
__device__ float g_sW[B_ * H_];     //   4 MiB
__device__ float g_gate[B_ * N_];   //   1 MiB
__device__ int g_flag_w[64];        // per 64-b tile: 10 producer blocks each
__device__ int g_flag_uv[4];        // per 16-n tile: 512 producer blocks each

// ---------- packed fp32x2 helpers (sm_103a FFMA2) ----------
__device__ __forceinline__ u64 pack2(float x, float y) {
    u64 r; asm("mov.b64 %0, {%1, %2};" : "=l"(r) : "f"(x), "f"(y)); return r;
}
__device__ __forceinline__ u64 fma2(u64 a, u64 b, u64 c) {
    u64 d; asm("fma.rn.f32x2 %0, %1, %2, %3;" : "=l"(d) : "l"(a), "l"(b), "l"(c)); return d;
}
__device__ __forceinline__ float2 unpack2(u64 v) {
    float2 r; asm("mov.b64 {%0, %1}, %2;" : "=f"(r.x), "=f"(r.y) : "l"(v)); return r;
}

__global__ void k_reset() {
    const int t = threadIdx.x;
    if (t < 64) g_flag_w[t] = 0;
    else if (t < 68) g_flag_uv[t - 64] = 0;
}

__device__ __forceinline__ void row_step(const float4 uv, const float4 hh,
                                         const float4 sw, const float g,
                                         const float a, float4& o, float& ss)
{
    float c, t;
    c = uv.x + sw.x; c = (c >= 0.f) ? c : a * c; t = fmaf(g, c, hh.x); o.x = t; ss = fmaf(t, t, ss);
    c = uv.y + sw.y; c = (c >= 0.f) ? c : a * c; t = fmaf(g, c, hh.y); o.y = t; ss = fmaf(t, t, ss);
    c = uv.z + sw.z; c = (c >= 0.f) ? c : a * c; t = fmaf(g, c, hh.z); o.z = t; ss = fmaf(t, t, ss);
    c = uv.w + sw.w; c = (c >= 0.f) ? c : a * c; t = fmaf(g, c, hh.w); o.w = t; ss = fmaf(t, t, ss);
}

// ---------------------------------------------------------------------------
// Mega kernel, one launch, three roles by blockIdx.x (producers first):
//  [0,640):      split-M GEMM: 64b x 32m tile per block (bt = blk/10,
//                sub = blk%10, m0 = 32*sub). Full K=256 per block, but the
//                per-warp serial path is HALVED vs the 64x64 tile (8 instr
//                per 8 MACs). sub<8 -> g_sW ; sub>=8 -> g_gate = sigmoid.
//                ++g_flag_w[bt] (to 10).
//  [640,2688):   UV (warp per element) -> g_UV; ++g_flag_uv[n/16] (to 512).
//  [2688,3712):  k3 (R2 measured-best body); volatile-load spin + backoff.
// Deadlock-free: producers have lower blockIdx and never wait.
// ---------------------------------------------------------------------------
__global__ void __launch_bounds__(256) mega(
    const float* __restrict__ s, const float* __restrict__ W,
    const float* __restrict__ h, const float* __restrict__ w,
    const float* __restrict__ U, const float* __restrict__ V,
    const float* __restrict__ a_ptr, float* __restrict__ out)
{
    __shared__ union {
        struct { float sa[32][64]; float sb[32][32]; } g;      // 12 KiB
        struct { float4 sw[2][64]; float gt[2][16]; } c;       //  2.2 KiB
    } sm;

    const int tid = threadIdx.x;
    const int blk = blockIdx.x;

    if (blk < NB_GEMM) {
        // ================= split-M GEMM =================
        const int bt = blk / 10;
        const int sub = blk % 10;
        const int b0 = bt * 64;
        const int m0 = sub * 32;                 // 0..288
        const bool gate_tile = (sub >= 8);       // m in [256,320) -> gate

        const int arow = tid & 63;               // A staging row
        const int akq = (tid >> 6) << 2;         // A k-quad: 0,4,8,12
        const int brow = tid & 31;               // B staging row (32 m-rows)
        const int bkq = (tid >> 5) << 2;         // B k-quad: 0,4,...,28
        const int tx = tid & 15;
        const int ty = tid >> 4;
        const int rb = ty << 2;                  // 4 b-rows (2 FFMA2 pairs)
        const int cm = tx << 1;                  // 2 m-cols

        u64 acc2[2][2] = {};

        float4 ra0, ra1, rbv;
        ra0 = *(const float4*)&s[(b0 + arow) * H_ + akq];
        ra1 = *(const float4*)&s[(b0 + arow) * H_ + 16 + akq];
        if (!gate_tile) {
            rbv = *(const float4*)&W[(m0 + brow) * H_ + bkq];
        } else {
            const int n = m0 - 256 + brow;
            float4 x = *(const float4*)&h[n * H_ + bkq];
            float4 y = *(const float4*)&w[n * H_ + bkq];
            rbv = make_float4(x.x + y.x, x.y + y.y, x.z + y.z, x.w + y.w);
        }

        for (int kc = 0; kc < H_; kc += 32) {
            sm.g.sa[akq + 0][arow] = ra0.x; sm.g.sa[akq + 1][arow] = ra0.y;
            sm.g.sa[akq + 2][arow] = ra0.z; sm.g.sa[akq + 3][arow] = ra0.w;
            sm.g.sa[16 + akq + 0][arow] = ra1.x; sm.g.sa[16 + akq + 1][arow] = ra1.y;
            sm.g.sa[16 + akq + 2][arow] = ra1.z; sm.g.sa[16 + akq + 3][arow] = ra1.w;
            sm.g.sb[bkq + 0][brow] = rbv.x; sm.g.sb[bkq + 1][brow] = rbv.y;
            sm.g.sb[bkq + 2][brow] = rbv.z; sm.g.sb[bkq + 3][brow] = rbv.w;
            __syncthreads();

            if (kc + 32 < H_) {
                const int kn = kc + 32;
                ra0 = *(const float4*)&s[(b0 + arow) * H_ + kn + akq];
                ra1 = *(const float4*)&s[(b0 + arow) * H_ + kn + 16 + akq];
                if (!gate_tile) {
                    rbv = *(const float4*)&W[(m0 + brow) * H_ + kn + bkq];
                } else {
                    const int n = m0 - 256 + brow;
                    float4 x = *(const float4*)&h[n * H_ + kn + bkq];
                    float4 y = *(const float4*)&w[n * H_ + kn + bkq];
                    rbv = make_float4(x.x + y.x, x.y + y.y, x.z + y.z, x.w + y.w);
                }
            }

#pragma unroll 8
            for (int k = 0; k < 32; ++k) {
                const ulonglong2 a2 = *(const ulonglong2*)&sm.g.sa[k][rb];
                const float2 bv = *(const float2*)&sm.g.sb[k][cm];
                const u64 bx = pack2(bv.x, bv.x);
                const u64 by = pack2(bv.y, bv.y);
                acc2[0][0] = fma2(a2.x, bx, acc2[0][0]);
                acc2[0][1] = fma2(a2.x, by, acc2[0][1]);
                acc2[1][0] = fma2(a2.y, bx, acc2[1][0]);
                acc2[1][1] = fma2(a2.y, by, acc2[1][1]);
            }
            __syncthreads();
        }

#pragma unroll
        for (int ib = 0; ib < 2; ++ib) {
            const float2 c0 = unpack2(acc2[ib][0]);   // m cm,   rows pair
            const float2 c1 = unpack2(acc2[ib][1]);   // m cm+1, rows pair
            const int bA = b0 + rb + 2 * ib;
            if (!gate_tile) {
                *(float2*)&g_sW[bA * H_ + m0 + cm] = make_float2(c0.x, c1.x);
                *(float2*)&g_sW[(bA + 1) * H_ + m0 + cm] = make_float2(c0.y, c1.y);
            } else {
                const int n = m0 - 256 + cm;
                *(float2*)&g_gate[bA * N_ + n] = make_float2(
                    1.0f / (1.0f + __expf(-c0.x)), 1.0f / (1.0f + __expf(-c1.x)));
                *(float2*)&g_gate[(bA + 1) * N_ + n] = make_float2(
                    1.0f / (1.0f + __expf(-c0.y)), 1.0f / (1.0f + __expf(-c1.y)));
            }
        }
        __threadfence();
        __syncthreads();
        if (tid == 0) atomicAdd(&g_flag_w[bt], 1);

    } else if (blk < NB_GEMM + NB_UV) {
        // ================= UV =================
        const int id = blk - NB_GEMM;
        const int n = id >> 5;
        const int kg = id & 31;
        const int warp = tid >> 5;
        const int lane = tid & 31;
        const int k = kg * 8 + warp;
        const int off = lane * 8;

        const float4* u4 = (const float4*)(U + k * H_ + off);
        const float4* v4 = (const float4*)(V + k * H_ + off);
        const float4* h4 = (const float4*)(h + n * H_ + off);
        const float4* w4 = (const float4*)(w + n * H_ + off);
        float4 u0 = u4[0], u1 = u4[1];
        float4 v0 = v4[0], v1 = v4[1];
        float4 x0 = __ldg(h4), x1 = __ldg(h4 + 1);
        float4 y0 = __ldg(w4), y1 = __ldg(w4 + 1);

        float acc = 0.f;
        acc = fmaf(u0.x, x0.x, acc); acc = fmaf(u0.y, x0.y, acc);
        acc = fmaf(u0.z, x0.z, acc); acc = fmaf(u0.w, x0.w, acc);
        acc = fmaf(u1.x, x1.x, acc); acc = fmaf(u1.y, x1.y, acc);
        acc = fmaf(u1.z, x1.z, acc); acc = fmaf(u1.w, x1.w, acc);
        acc = fmaf(v0.x, y0.x, acc); acc = fmaf(v0.y, y0.y, acc);
        acc = fmaf(v0.z, y0.z, acc); acc = fmaf(v0.w, y0.w, acc);
        acc = fmaf(v1.x, y1.x, acc); acc = fmaf(v1.y, y1.y, acc);
        acc = fmaf(v1.z, y1.z, acc); acc = fmaf(v1.w, y1.w, acc);

#pragma unroll
        for (int o = 16; o > 0; o >>= 1)
            acc += __shfl_xor_sync(0xFFFFFFFFu, acc, o);
        if (lane == 0) g_UV[n * H_ + k] = acc;

        __threadfence();
        __syncthreads();
        if (tid == 0) atomicAdd(&g_flag_uv[n >> 4], 1);

    } else {
        // ================= k3 (consumer, R2 body) =================
        const int id = blk - (NB_GEMM + NB_UV);
        const int n0 = (id & 3) * 16;
        const int b0 = (id >> 2) * TB3;
        const int bt = b0 >> 6;

        const int warp = tid >> 5;
        const int lane = tid & 31;
        const int nA = n0 + warp;
        const int nB = n0 + warp + 8;
        const int k0 = lane * 4;
        const int k1 = 128 + lane * 4;

        // Pure inputs: load before waiting (overlaps the spin).
        float4 hA0 = __ldg((const float4*)&h[nA * H_ + k0]);
        float4 hA1 = __ldg((const float4*)&h[nA * H_ + k1]);
        float4 hB0 = __ldg((const float4*)&h[nB * H_ + k0]);
        float4 hB1 = __ldg((const float4*)&h[nB * H_ + k1]);
        const float a = __ldg(a_ptr);

        // Volatile-load spin with backoff (no atomic storm).
        if (tid == 0) {
            while (((volatile int*)g_flag_w)[bt] < 10) __nanosleep(128);
            while (((volatile int*)g_flag_uv)[n0 >> 4] < 512) __nanosleep(128);
            __threadfence();
        }
        __syncthreads();

        float4 uvA0 = *(const float4*)&g_UV[nA * H_ + k0];
        float4 uvA1 = *(const float4*)&g_UV[nA * H_ + k1];
        float4 uvB0 = *(const float4*)&g_UV[nB * H_ + k0];
        float4 uvB1 = *(const float4*)&g_UV[nB * H_ + k1];

        if (tid < 64) sm.c.sw[0][tid] = __ldg((const float4*)&g_sW[(size_t)b0 * H_] + tid);
        else if (tid < 80) sm.c.gt[0][tid - 64] = __ldg(&g_gate[b0 * N_ + n0 + (tid - 64)]);
        __syncthreads();

        for (int i = 0; i < TB3; ++i) {
            const int buf = i & 1;
            if (i + 1 < TB3) {
                const int bn = b0 + i + 1;
                if (tid < 64) sm.c.sw[buf ^ 1][tid] = __ldg((const float4*)&g_sW[(size_t)bn * H_] + tid);
                else if (tid < 80) sm.c.gt[buf ^ 1][tid - 64] = __ldg(&g_gate[bn * N_ + n0 + (tid - 64)]);
            }

            const float4 s0 = sm.c.sw[buf][lane];
            const float4 s1 = sm.c.sw[buf][lane + 32];
            const float gA = sm.c.gt[buf][warp];
            const float gB = sm.c.gt[buf][warp + 8];

            float4 oA0, oA1, oB0, oB1;
            float ssA = 0.f, ssB = 0.f;
            row_step(uvA0, hA0, s0, gA, a, oA0, ssA);
            row_step(uvA1, hA1, s1, gA, a, oA1, ssA);
            row_step(uvB0, hB0, s0, gB, a, oB0, ssB);
            row_step(uvB1, hB1, s1, gB, a, oB1, ssB);

#pragma unroll
            for (int o = 16; o > 0; o >>= 1) {
                ssA += __shfl_xor_sync(0xFFFFFFFFu, ssA, o);
                ssB += __shfl_xor_sync(0xFFFFFFFFu, ssB, o);
            }
            const float iA = rsqrtf(ssA);
            const float iB = rsqrtf(ssB);

            const int b = b0 + i;
            float4* oA = (float4*)&out[((size_t)b * N_ + nA) * H_];
            float4* oB = (float4*)&out[((size_t)b * N_ + nB) * H_];
            oA[lane]      = make_float4(oA0.x * iA, oA0.y * iA, oA0.z * iA, oA0.w * iA);
            oA[32 + lane] = make_float4(oA1.x * iA, oA1.y * iA, oA1.z * iA, oA1.w * iA);
            oB[lane]      = make_float4(oB0.x * iB, oB0.y * iB, oB0.z * iB, oB0.w * iB);
            oB[32 + lane] = make_float4(oB1.x * iB, oB1.y * iB, oB1.z * iB, oB1.w * iB);

            __syncthreads();
        }
    }
}

// ---------------------------------------------------------------------------
extern "C" void kernel_launch(void* const* d_in, const int* in_sizes, int n_in,
                              void* d_out, int out_size)
{
    const float* s_t = (const float*)d_in[0];   // [B,H]
    const float* h   = (const float*)d_in[1];   // [1,N,H]
    const float* w   = (const float*)d_in[2];   // [1,N,H]
    const float* U   = (const float*)d_in[3];   // [H,H]
    const float* V   = (const float*)d_in[4];   // [H,H]
    const float* W   = (const float*)d_in[5];   // [H,H]
    const float* pa  = (const float*)d_in[6];   // [1]
    float* out = (float*)d_out;                 // [B,N,H]

    k_reset<<<1, 128>>>();
    mega<<<NB_GEMM + NB_UV + NB_K3, 256>>>(s_t, W, h, w, U, V, pa, out);
}